// round 7
// baseline (speedup 1.0000x reference)
#include <cuda_runtime.h>
#include <cuda_bf16.h>
#include <float.h>
#include <math.h>

// ---------------- problem constants ----------------
#define NL   12
#define D    768
#define NH   12
#define HD   64
#define VV   50257
#define VPAD 50304            // 393 * 128
#define BB   4
#define TT   1024
#define BT   (BB*TT)          // 4096
#define FF   (4*D)            // 3072
#define BH   (BB*NH)          // 48
#define EPSF 1e-5f
#define SCALE 0.125f          // HD^-0.5

// ---------------- scratch (device globals; no runtime alloc) ----------------
__device__ float g_x[BT*D];
__device__ float g_h[BT*D];
__device__ float g_q[BT*D];
__device__ float g_k[BT*D];
__device__ float g_v[BT*D];
__device__ float g_o[BT*D];
__device__ float g_ff[BT*FF];
__device__ float g_att[(size_t)BH*TT*TT];   // 201 MB
__device__ float g_nll[BT];
__device__ float g_wlm[(size_t)D*VPAD];     // padded LM-head weight (155 MB)

// ---------------- tf32 / async helpers ----------------
__device__ __forceinline__ unsigned f2tf(float x) {
    unsigned r;
    asm("cvt.rna.tf32.f32 %0, %1;" : "=r"(r) : "f"(x));
    return r;
}
__device__ __forceinline__ float tf32f(float x) { return __uint_as_float(f2tf(x)); }

__device__ __forceinline__ void mma_tf32(float* d, const unsigned* a, const unsigned* b) {
    asm volatile(
        "mma.sync.aligned.m16n8k8.row.col.f32.tf32.tf32.f32 "
        "{%0,%1,%2,%3}, {%4,%5,%6,%7}, {%8,%9}, {%0,%1,%2,%3};"
        : "+f"(d[0]), "+f"(d[1]), "+f"(d[2]), "+f"(d[3])
        : "r"(a[0]), "r"(a[1]), "r"(a[2]), "r"(a[3]), "r"(b[0]), "r"(b[1]));
}
__device__ __forceinline__ void cp16(void* s, const void* g) {
    unsigned sa = (unsigned)__cvta_generic_to_shared(s);
    asm volatile("cp.async.cg.shared.global [%0], [%1], 16;" :: "r"(sa), "l"(g));
}
#define CP_COMMIT() asm volatile("cp.async.commit_group;")
#define CP_WAIT1()  asm volatile("cp.async.wait_group 1;")

// ---------------- tf32 rounding pass ----------------
__global__ void round_kernel(const float* __restrict__ in, float* __restrict__ out,
                             long long n) {
    long long i = (long long)blockIdx.x * blockDim.x + threadIdx.x;
    long long stride = (long long)gridDim.x * blockDim.x;
    for (; i < n; i += stride) out[i] = tf32f(in[i]);
}

// ---------------- LM weight padding: [D][VV] -> [D][VPAD] (zero-filled) ----------------
__global__ void pad_wlm_kernel(const float* __restrict__ w, float* __restrict__ out) {
    int col = blockIdx.x * 256 + threadIdx.x;
    int row = blockIdx.y;
    if (col < VPAD)
        out[(size_t)row * VPAD + col] = (col < VV) ? w[(size_t)row * VV + col] : 0.f;
}

// ---------------- embedding ----------------
__global__ void embed_kernel(const int* __restrict__ idx,
                             const float* __restrict__ tok,
                             const float* __restrict__ pos,
                             float* __restrict__ x) {
    int i = blockIdx.x * 256 + threadIdx.x;
    if (i >= BT * D) return;
    int row = i / D;
    int d   = i - row * D;
    int t   = row & (TT - 1);
    x[i] = tok[(size_t)idx[row] * D + d] + pos[(size_t)t * D + d];
}

// ---------------- layernorm (output pre-rounded to tf32) ----------------
__global__ void ln_kernel(const float* __restrict__ x,
                          const float* __restrict__ g,
                          const float* __restrict__ b,
                          float* __restrict__ out) {
    int row = blockIdx.x;
    const float* xr = x + (size_t)row * D;
    __shared__ float sx[D];
    __shared__ float red[256];
    int tid = threadIdx.x;

    float s = 0.f;
    for (int i = tid; i < D; i += 256) { float t = xr[i]; sx[i] = t; s += t; }
    red[tid] = s; __syncthreads();
    #pragma unroll
    for (int off = 128; off > 0; off >>= 1) {
        if (tid < off) red[tid] += red[tid + off];
        __syncthreads();
    }
    float mean = red[0] * (1.f / D);
    __syncthreads();

    float s2 = 0.f;
    for (int i = tid; i < D; i += 256) { float t = sx[i] - mean; s2 += t * t; }
    red[tid] = s2; __syncthreads();
    #pragma unroll
    for (int off = 128; off > 0; off >>= 1) {
        if (tid < off) red[tid] += red[tid + off];
        __syncthreads();
    }
    float rstd = rsqrtf(red[0] * (1.f / D) + EPSF);

    float* orow = out + (size_t)row * D;
    for (int i = tid; i < D; i += 256)
        orow[i] = tf32f((sx[i] - mean) * rstd * g[i] + b[i]);
}

// ---------------- TF32 tensor-core GEMM ----------------
// C[M, Ncols] = A[M,K] @ B[K, ldB-wide] (+bias)(+resid)(relu?)(roundC?)
// Block 128x128x32, 128 threads = 4 warps as 2(M)x2(N), warp tile 64x64.
// 2-stage cp.async; A pre-rounded tf32; B cvt.rna on fragment load.
// Requires: M mult 128, K mult 32, ldB mult 4, grid.y*128 <= ldB.
#define AK    36
#define BNW   136
#define ASTG  (128*AK)          // 4608
#define BSTG  (32*BNW)          // 4352
#define BOFF  (2*ASTG)
#define GSMEM ((2*ASTG + 2*BSTG) * 4)   // 71680 bytes

__global__ __launch_bounds__(128, 2)
void gemm_tf32(const float* __restrict__ A, const float* __restrict__ Bm,
               const float* __restrict__ bias, const float* __restrict__ resid,
               float* __restrict__ C, int M, int Ncols, int K, int ldB, int ldC,
               int relu, int roundC) {
    extern __shared__ float smem[];

    const int tid  = threadIdx.x;
    const int lane = tid & 31;
    const int wid  = tid >> 5;
    const int warpM = (wid >> 1) * 64;   // 0,64
    const int warpN = (wid & 1) * 64;    // 0,64
    const int gm = blockIdx.x * 128;
    const int gn = blockIdx.y * 128;
    const int lt = lane & 3;
    const int lg = lane >> 2;

    float acc[4][8][4];
    #pragma unroll
    for (int mi = 0; mi < 4; mi++)
        #pragma unroll
        for (int nj = 0; nj < 8; nj++)
            #pragma unroll
            for (int r = 0; r < 4; r++) acc[mi][nj][r] = 0.f;

    const int nch = K >> 5;

    auto load_tiles = [&](int k0, int stage) {
        float* As = smem + stage * ASTG;
        float* Bs = smem + BOFF + stage * BSTG;
        #pragma unroll
        for (int i = 0; i < 8; i++) {
            int c  = tid + i * 128;        // 0..1023 : A 128x32
            int m  = c >> 3;
            int k4 = (c & 7) << 2;
            cp16(As + m * AK + k4, A + (size_t)(gm + m) * K + k0 + k4);
        }
        #pragma unroll
        for (int i = 0; i < 8; i++) {
            int c  = tid + i * 128;        // 0..1023 : B 32x128
            int kr = c >> 5;
            int n4 = (c & 31) << 2;
            cp16(Bs + kr * BNW + n4, Bm + (size_t)(k0 + kr) * ldB + gn + n4);
        }
    };

    load_tiles(0, 0);
    CP_COMMIT();

    for (int ch = 0; ch < nch; ch++) {
        int stage = ch & 1;
        if (ch + 1 < nch) load_tiles((ch + 1) << 5, stage ^ 1);
        CP_COMMIT();
        CP_WAIT1();
        __syncthreads();

        const float* Asb = smem + stage * ASTG;
        const float* Bsb = smem + BOFF + stage * BSTG;

        #pragma unroll
        for (int kk = 0; kk < 32; kk += 8) {
            unsigned a[4][4], b[8][2];
            #pragma unroll
            for (int mi = 0; mi < 4; mi++) {
                const float* p0 = Asb + (warpM + mi * 16 + lg) * AK + kk;
                const float* p1 = p0 + 8 * AK;
                a[mi][0] = __float_as_uint(p0[lt]);
                a[mi][1] = __float_as_uint(p1[lt]);
                a[mi][2] = __float_as_uint(p0[lt + 4]);
                a[mi][3] = __float_as_uint(p1[lt + 4]);
            }
            #pragma unroll
            for (int nj = 0; nj < 8; nj++) {
                int nc = warpN + nj * 8 + lg;
                b[nj][0] = f2tf(Bsb[(kk + lt) * BNW + nc]);
                b[nj][1] = f2tf(Bsb[(kk + lt + 4) * BNW + nc]);
            }
            #pragma unroll
            for (int mi = 0; mi < 4; mi++)
                #pragma unroll
                for (int nj = 0; nj < 8; nj++)
                    mma_tf32(acc[mi][nj], a[mi], b[nj]);
        }
        __syncthreads();
    }

    // ---- epilogue ----
    #pragma unroll
    for (int mi = 0; mi < 4; mi++) {
        int r0 = gm + warpM + mi * 16 + lg;
        #pragma unroll
        for (int nj = 0; nj < 8; nj++) {
            int c0 = gn + warpN + nj * 8 + (lt << 1);
            #pragma unroll
            for (int r = 0; r < 4; r++) {
                int rowg = r0 + ((r >> 1) << 3);
                int colg = c0 + (r & 1);
                if (colg < Ncols) {
                    float v = acc[mi][nj][r];
                    if (bias)   v += bias[colg];
                    if (resid)  v += resid[(size_t)rowg * ldC + colg];
                    if (relu)   v = fmaxf(v, 0.f);
                    if (roundC) v = tf32f(v);
                    C[(size_t)rowg * ldC + colg] = v;
                }
            }
        }
    }
}

// ---------------- attention scores via tf32 mma: scale * Q K^T + causal ----------------
#define QP 68
#define KP 65
__global__ __launch_bounds__(128)
void attn_scores(const float* __restrict__ q, const float* __restrict__ k,
                 float* __restrict__ att) {
    int tb = blockIdx.x, sb = blockIdx.y, bh = blockIdx.z;
    if (sb > tb) return;
    int b = bh / NH, h = bh % NH;

    __shared__ float Qs[64 * QP];   // [m][d]
    __shared__ float Ks[64 * KP];   // [d][s]
    const int tid  = threadIdx.x;
    const int lane = tid & 31;
    const int wid  = tid >> 5;
    const int warpM = (wid >> 1) * 32;
    const int warpN = (wid & 1) * 32;
    const int lt = lane & 3;
    const int lg = lane >> 2;

    const float* qb = q + (size_t)b * TT * D + (size_t)h * HD;
    const float* kb = k + (size_t)b * TT * D + (size_t)h * HD;

    #pragma unroll
    for (int i = 0; i < 8; i++) {
        int c  = tid + i * 128;
        int m  = c >> 4;
        int d4 = (c & 15) << 2;
        *(float4*)(Qs + m * QP + d4) =
            *(const float4*)(qb + (size_t)(tb * 64 + m) * D + d4);
    }
    #pragma unroll
    for (int i = 0; i < 32; i++) {
        int c = tid + i * 128;
        int s = c >> 6;
        int d = c & 63;
        Ks[d * KP + s] = kb[(size_t)(sb * 64 + s) * D + d];
    }
    __syncthreads();

    float acc[2][4][4];
    #pragma unroll
    for (int mi = 0; mi < 2; mi++)
        #pragma unroll
        for (int nj = 0; nj < 4; nj++)
            #pragma unroll
            for (int r = 0; r < 4; r++) acc[mi][nj][r] = 0.f;

    #pragma unroll
    for (int kk = 0; kk < 64; kk += 8) {
        unsigned a[2][4], bfr[4][2];
        #pragma unroll
        for (int mi = 0; mi < 2; mi++) {
            const float* p0 = Qs + (warpM + mi * 16 + lg) * QP + kk;
            const float* p1 = p0 + 8 * QP;
            a[mi][0] = f2tf(p0[lt]);
            a[mi][1] = f2tf(p1[lt]);
            a[mi][2] = f2tf(p0[lt + 4]);
            a[mi][3] = f2tf(p1[lt + 4]);
        }
        #pragma unroll
        for (int nj = 0; nj < 4; nj++) {
            int nc = warpN + nj * 8 + lg;
            bfr[nj][0] = f2tf(Ks[(kk + lt) * KP + nc]);
            bfr[nj][1] = f2tf(Ks[(kk + lt + 4) * KP + nc]);
        }
        #pragma unroll
        for (int mi = 0; mi < 2; mi++)
            #pragma unroll
            for (int nj = 0; nj < 4; nj++)
                mma_tf32(acc[mi][nj], a[mi], bfr[nj]);
    }

    float* out = att + ((size_t)bh * TT + (size_t)tb * 64) * TT + (size_t)sb * 64;
    #pragma unroll
    for (int mi = 0; mi < 2; mi++) {
        int tl0 = warpM + mi * 16 + lg;
        #pragma unroll
        for (int nj = 0; nj < 4; nj++) {
            int sl0 = warpN + nj * 8 + (lt << 1);
            #pragma unroll
            for (int r = 0; r < 4; r++) {
                int tl = tl0 + ((r >> 1) << 3);
                int sl = sl0 + (r & 1);
                int tg = tb * 64 + tl;
                int sg = sb * 64 + sl;
                out[(size_t)tl * TT + sl] =
                    (sg <= tg) ? acc[mi][nj][r] * SCALE : -3.402823466e38f;
            }
        }
    }
}

// ---------------- attention row softmax (fast exp) ----------------
__global__ void attn_softmax(float* __restrict__ att) {
    int row = blockIdx.x;
    int t = row & (TT - 1);
    float* p = att + (size_t)row * TT;
    int L = ((t >> 6) + 1) << 6;
    int tid = threadIdx.x;

    float m = -FLT_MAX;
    for (int i = tid; i < L; i += 256) m = fmaxf(m, p[i]);
    __shared__ float sm[256], ss[256];
    sm[tid] = m; __syncthreads();
    #pragma unroll
    for (int off = 128; off > 0; off >>= 1) {
        if (tid < off) sm[tid] = fmaxf(sm[tid], sm[tid + off]);
        __syncthreads();
    }
    float gm = sm[0];

    float s = 0.f;
    for (int i = tid; i < L; i += 256) s += __expf(p[i] - gm);
    ss[tid] = s; __syncthreads();
    #pragma unroll
    for (int off = 128; off > 0; off >>= 1) {
        if (tid < off) ss[tid] += ss[tid + off];
        __syncthreads();
    }
    float inv = 1.f / ss[0];
    for (int i = tid; i < L; i += 256)
        p[i] = __expf(p[i] - gm) * inv;
}

// ---------------- attention PV via tf32 mma: O = P @ V ----------------
#define PP 68
#define VP 68
__global__ __launch_bounds__(128)
void attn_pv(const float* __restrict__ att, const float* __restrict__ v,
             float* __restrict__ o) {
    int tb = blockIdx.x, bh = blockIdx.y;
    int b = bh / NH, h = bh % NH;

    __shared__ float Ps[64 * PP];   // [t][s]
    __shared__ float Vs[64 * VP];   // [s][d]
    const int tid  = threadIdx.x;
    const int lane = tid & 31;
    const int wid  = tid >> 5;
    const int warpM = (wid >> 1) * 32;
    const int warpN = (wid & 1) * 32;
    const int lt = lane & 3;
    const int lg = lane >> 2;

    const float* arow = att + ((size_t)bh * TT + (size_t)tb * 64) * TT;
    const float* vb = v + (size_t)b * TT * D + (size_t)h * HD;
    int Smax = (tb + 1) * 64;

    float acc[2][4][4];
    #pragma unroll
    for (int mi = 0; mi < 2; mi++)
        #pragma unroll
        for (int nj = 0; nj < 4; nj++)
            #pragma unroll
            for (int r = 0; r < 4; r++) acc[mi][nj][r] = 0.f;

    for (int s0 = 0; s0 < Smax; s0 += 64) {
        #pragma unroll
        for (int i = 0; i < 8; i++) {
            int c  = tid + i * 128;
            int m  = c >> 4;
            int s4 = (c & 15) << 2;
            *(float4*)(Ps + m * PP + s4) =
                *(const float4*)(arow + (size_t)m * TT + s0 + s4);
            *(float4*)(Vs + m * VP + s4) =
                *(const float4*)(vb + (size_t)(s0 + m) * D + s4);
        }
        __syncthreads();

        #pragma unroll
        for (int kk = 0; kk < 64; kk += 8) {
            unsigned a[2][4], bfr[4][2];
            #pragma unroll
            for (int mi = 0; mi < 2; mi++) {
                const float* p0 = Ps + (warpM + mi * 16 + lg) * PP + kk;
                const float* p1 = p0 + 8 * PP;
                a[mi][0] = f2tf(p0[lt]);
                a[mi][1] = f2tf(p1[lt]);
                a[mi][2] = f2tf(p0[lt + 4]);
                a[mi][3] = f2tf(p1[lt + 4]);
            }
            #pragma unroll
            for (int nj = 0; nj < 4; nj++) {
                int nc = warpN + nj * 8 + lg;
                bfr[nj][0] = f2tf(Vs[(kk + lt) * VP + nc]);
                bfr[nj][1] = f2tf(Vs[(kk + lt + 4) * VP + nc]);
            }
            #pragma unroll
            for (int mi = 0; mi < 2; mi++)
                #pragma unroll
                for (int nj = 0; nj < 4; nj++)
                    mma_tf32(acc[mi][nj], a[mi], bfr[nj]);
        }
        __syncthreads();
    }

    float* ob = o + (size_t)(b * TT + tb * 64) * D + (size_t)h * HD;
    #pragma unroll
    for (int mi = 0; mi < 2; mi++) {
        int tl0 = warpM + mi * 16 + lg;
        #pragma unroll
        for (int nj = 0; nj < 4; nj++) {
            int dl0 = warpN + nj * 8 + (lt << 1);
            #pragma unroll
            for (int r = 0; r < 4; r++) {
                int tl = tl0 + ((r >> 1) << 3);
                int dl = dl0 + (r & 1);
                ob[(size_t)tl * D + dl] = tf32f(acc[mi][nj][r]);
            }
        }
    }
}

// ---------------- per-row NLL over vocab ----------------
__global__ void nll_kernel(const float* __restrict__ logits,
                           const int* __restrict__ targets,
                           float* __restrict__ nll) {
    int row = blockIdx.x;
    const float* lr = logits + (size_t)row * VV;
    int tid = threadIdx.x;
    __shared__ float red[256];

    float m = -FLT_MAX;
    for (int i = tid; i < VV; i += 256) m = fmaxf(m, lr[i]);
    red[tid] = m; __syncthreads();
    #pragma unroll
    for (int off = 128; off > 0; off >>= 1) {
        if (tid < off) red[tid] = fmaxf(red[tid], red[tid + off]);
        __syncthreads();
    }
    float gm = red[0];
    __syncthreads();

    float s0 = 0.f, s1 = 0.f, s2 = 0.f, s3 = 0.f;
    int i = tid;
    for (; i + 768 < VV; i += 1024) {
        s0 += __expf(lr[i]       - gm);
        s1 += __expf(lr[i + 256] - gm);
        s2 += __expf(lr[i + 512] - gm);
        s3 += __expf(lr[i + 768] - gm);
    }
    for (; i < VV; i += 256) s0 += __expf(lr[i] - gm);
    red[tid] = (s0 + s1) + (s2 + s3); __syncthreads();
    #pragma unroll
    for (int off = 128; off > 0; off >>= 1) {
        if (tid < off) red[tid] += red[tid + off];
        __syncthreads();
    }
    if (tid == 0)
        nll[row] = gm + logf(red[0]) - lr[targets[row]];
}

__global__ void loss_kernel(const float* __restrict__ nll, float* __restrict__ dst,
                            int nextra) {
    __shared__ float red[256];
    int tid = threadIdx.x;
    float s = 0.f;
    for (int i = tid; i < BT; i += 256) s += nll[i];
    red[tid] = s; __syncthreads();
    #pragma unroll
    for (int off = 128; off > 0; off >>= 1) {
        if (tid < off) red[tid] += red[tid + off];
        __syncthreads();
    }
    if (tid == 0) {
        float loss = red[0] * (1.f / BT);
        for (int i = 0; i < nextra; i++) dst[i] = loss;
    }
}

// ---------------- launch ----------------
extern "C" void kernel_launch(void* const* d_in, const int* in_sizes, int n_in,
                              void* d_out, int out_size) {
    const int*   idx     = (const int*)  d_in[0];
    const int*   targets = (const int*)  d_in[1];
    const float* tok_emb = (const float*)d_in[2];
    const float* pos_emb = (const float*)d_in[3];
    const float* Wq      = (const float*)d_in[4];
    const float* Wk      = (const float*)d_in[5];
    const float* Wv      = (const float*)d_in[6];
    const float* Wo      = (const float*)d_in[7];
    const float* bo      = (const float*)d_in[8];
    const float* ln1_g   = (const float*)d_in[9];
    const float* ln1_b   = (const float*)d_in[10];
    const float* ln2_g   = (const float*)d_in[11];
    const float* ln2_b   = (const float*)d_in[12];
    const float* W1      = (const float*)d_in[13];
    const float* b1      = (const float*)d_in[14];
    const float* W2      = (const float*)d_in[15];
    const float* b2      = (const float*)d_in[16];
    const float* Wlm     = (const float*)d_in[17];
    const float* blm     = (const float*)d_in[18];

    float *x, *h, *q, *k, *v, *o, *ff, *att, *nll, *wlm;
    cudaGetSymbolAddress((void**)&x,   g_x);
    cudaGetSymbolAddress((void**)&h,   g_h);
    cudaGetSymbolAddress((void**)&q,   g_q);
    cudaGetSymbolAddress((void**)&k,   g_k);
    cudaGetSymbolAddress((void**)&v,   g_v);
    cudaGetSymbolAddress((void**)&o,   g_o);
    cudaGetSymbolAddress((void**)&ff,  g_ff);
    cudaGetSymbolAddress((void**)&att, g_att);
    cudaGetSymbolAddress((void**)&nll, g_nll);
    cudaGetSymbolAddress((void**)&wlm, g_wlm);

    cudaFuncSetAttribute(gemm_tf32, cudaFuncAttributeMaxDynamicSharedMemorySize, GSMEM);

    // pad LM-head weight to VPAD columns (zero-filled)
    pad_wlm_kernel<<<dim3((VPAD + 255) / 256, D), 256>>>(Wlm, wlm);

    embed_kernel<<<(BT * D + 255) / 256, 256>>>(idx, tok_emb, pos_emb, x);

    dim3 gD(BT / 128, D / 128);              // 32 x 6
    dim3 gF(BT / 128, FF / 128);             // 32 x 24
    dim3 gV(BT / 128, VPAD / 128);           // 32 x 393

    for (int l = 0; l < NL; l++) {
        const float* wq = Wq + (size_t)l * D * D;
        const float* wk = Wk + (size_t)l * D * D;
        const float* wv = Wv + (size_t)l * D * D;
        const float* wo = Wo + (size_t)l * D * D;
        const float* w1 = W1 + (size_t)l * D * FF;
        const float* w2 = W2 + (size_t)l * FF * D;

        ln_kernel<<<BT, 256>>>(x, ln1_g + (size_t)l * D, ln1_b + (size_t)l * D, h);
        gemm_tf32<<<gD, 128, GSMEM>>>(h, wq, nullptr, nullptr, q, BT, D, D, D, D, 0, 0);
        gemm_tf32<<<gD, 128, GSMEM>>>(h, wk, nullptr, nullptr, k, BT, D, D, D, D, 0, 0);
        gemm_tf32<<<gD, 128, GSMEM>>>(h, wv, nullptr, nullptr, v, BT, D, D, D, D, 0, 0);

        attn_scores<<<dim3(TT / 64, TT / 64, BH), 128>>>(q, k, att);
        attn_softmax<<<BH * TT, 256>>>(att);
        attn_pv<<<dim3(TT / 64, BH), 128>>>(att, v, o);

        gemm_tf32<<<gD, 128, GSMEM>>>(o, wo, bo + (size_t)l * D, x, x, BT, D, D, D, D, 0, 0);

        ln_kernel<<<BT, 256>>>(x, ln2_g + (size_t)l * D, ln2_b + (size_t)l * D, h);
        gemm_tf32<<<gF, 128, GSMEM>>>(h, w1, b1 + (size_t)l * FF, nullptr, ff, BT, FF, D, FF, FF, 1, 1);
        gemm_tf32<<<gD, 128, GSMEM>>>(ff, w2, b2 + (size_t)l * D, x, x, BT, D, FF, D, D, 0, 0);
    }

    // rounded copy of x for the LM head A operand
    round_kernel<<<1024, 256>>>(x, h, (long long)BT * D);

    float* logits = (float*)d_out;
    gemm_tf32<<<gV, 128, GSMEM>>>(h, wlm, blm, nullptr, logits, BT, VV, D, VPAD, VV, 0, 0);

    long long btv = (long long)BT * VV;
    if ((long long)out_size > btv) {
        nll_kernel<<<BT, 256>>>(logits, targets, nll);
        loss_kernel<<<1, 256>>>(nll, logits + btv, (int)((long long)out_size - btv));
    }
}

// round 8
// speedup vs baseline: 1.0624x; 1.0624x over previous
#include <cuda_runtime.h>
#include <cuda_bf16.h>
#include <float.h>
#include <math.h>

// ---------------- problem constants ----------------
#define NL   12
#define D    768
#define NH   12
#define HD   64
#define VV   50257
#define VPAD 50304            // 393 * 128
#define BB   4
#define TT   1024
#define BT   (BB*TT)          // 4096
#define FF   (4*D)            // 3072
#define BH   (BB*NH)          // 48
#define EPSF 1e-5f
#define SCALE 0.125f          // HD^-0.5

// ---------------- scratch (device globals; no runtime alloc) ----------------
__device__ float g_x[BT*D];
__device__ float g_h[BT*D];
__device__ float g_q[BT*D];
__device__ float g_k[BT*D];
__device__ float g_v[BT*D];
__device__ float g_o[BT*D];
__device__ float g_ff[BT*FF];
__device__ float g_att[(size_t)BH*TT*TT];   // 201 MB
__device__ float g_nll[BT];
__device__ float g_wlm[(size_t)D*VPAD];     // padded LM-head weight (155 MB)

// ---------------- tf32 / async helpers ----------------
__device__ __forceinline__ unsigned f2tf(float x) {
    unsigned r;
    asm("cvt.rna.tf32.f32 %0, %1;" : "=r"(r) : "f"(x));
    return r;
}
__device__ __forceinline__ float tf32f(float x) { return __uint_as_float(f2tf(x)); }

__device__ __forceinline__ void mma_tf32(float* d, const unsigned* a, const unsigned* b) {
    asm volatile(
        "mma.sync.aligned.m16n8k8.row.col.f32.tf32.tf32.f32 "
        "{%0,%1,%2,%3}, {%4,%5,%6,%7}, {%8,%9}, {%0,%1,%2,%3};"
        : "+f"(d[0]), "+f"(d[1]), "+f"(d[2]), "+f"(d[3])
        : "r"(a[0]), "r"(a[1]), "r"(a[2]), "r"(a[3]), "r"(b[0]), "r"(b[1]));
}
__device__ __forceinline__ void cp16(void* s, const void* g) {
    unsigned sa = (unsigned)__cvta_generic_to_shared(s);
    asm volatile("cp.async.cg.shared.global [%0], [%1], 16;" :: "r"(sa), "l"(g));
}
#define CP_COMMIT() asm volatile("cp.async.commit_group;")
#define CP_WAIT1()  asm volatile("cp.async.wait_group 1;")

// ---------------- tf32 rounding pass ----------------
__global__ void round_kernel(const float* __restrict__ in, float* __restrict__ out,
                             long long n) {
    long long i = (long long)blockIdx.x * blockDim.x + threadIdx.x;
    long long stride = (long long)gridDim.x * blockDim.x;
    for (; i < n; i += stride) out[i] = tf32f(in[i]);
}

// ---------------- LM weight padding: [D][VV] -> [D][VPAD] (zero-filled) ----------------
__global__ void pad_wlm_kernel(const float* __restrict__ w, float* __restrict__ out) {
    int col = blockIdx.x * 256 + threadIdx.x;
    int row = blockIdx.y;
    if (col < VPAD)
        out[(size_t)row * VPAD + col] = (col < VV) ? w[(size_t)row * VV + col] : 0.f;
}

// ---------------- embedding ----------------
__global__ void embed_kernel(const int* __restrict__ idx,
                             const float* __restrict__ tok,
                             const float* __restrict__ pos,
                             float* __restrict__ x) {
    int i = blockIdx.x * 256 + threadIdx.x;
    if (i >= BT * D) return;
    int row = i / D;
    int d   = i - row * D;
    int t   = row & (TT - 1);
    x[i] = tok[(size_t)idx[row] * D + d] + pos[(size_t)t * D + d];
}

// ---------------- layernorm (output pre-rounded to tf32) ----------------
__global__ void ln_kernel(const float* __restrict__ x,
                          const float* __restrict__ g,
                          const float* __restrict__ b,
                          float* __restrict__ out) {
    int row = blockIdx.x;
    const float* xr = x + (size_t)row * D;
    __shared__ float sx[D];
    __shared__ float red[256];
    int tid = threadIdx.x;

    float s = 0.f;
    for (int i = tid; i < D; i += 256) { float t = xr[i]; sx[i] = t; s += t; }
    red[tid] = s; __syncthreads();
    #pragma unroll
    for (int off = 128; off > 0; off >>= 1) {
        if (tid < off) red[tid] += red[tid + off];
        __syncthreads();
    }
    float mean = red[0] * (1.f / D);
    __syncthreads();

    float s2 = 0.f;
    for (int i = tid; i < D; i += 256) { float t = sx[i] - mean; s2 += t * t; }
    red[tid] = s2; __syncthreads();
    #pragma unroll
    for (int off = 128; off > 0; off >>= 1) {
        if (tid < off) red[tid] += red[tid + off];
        __syncthreads();
    }
    float rstd = rsqrtf(red[0] * (1.f / D) + EPSF);

    float* orow = out + (size_t)row * D;
    for (int i = tid; i < D; i += 256)
        orow[i] = tf32f((sx[i] - mean) * rstd * g[i] + b[i]);
}

// ---------------- TF32 tensor-core GEMM (R6 core + ld/Ncols params) ----------------
// C[M, Ncols] = A[M,K] @ B[K, ldB] (+bias)(+resid)(relu?)(roundC?)
// Block 128x64x32, 128 threads = 4 warps as 2(M)x2(N), warp tile 64x32.
// 2-stage cp.async; A pre-rounded tf32; B raw fp32 (cvt.rna on fragment load).
// Requires: M mult 128, K mult 32, ldB mult 4, grid.y*64 <= ldB.
#define AK    36
#define BN2   68
#define ASTG  (128*AK)          // 4608
#define BSTG  (32*BN2)          // 2176
#define BOFF  (2*ASTG)
#define GSMEM ((2*ASTG + 2*BSTG) * 4)   // 54272 bytes

__global__ __launch_bounds__(128, 3)
void gemm_tf32(const float* __restrict__ A, const float* __restrict__ Bm,
               const float* __restrict__ bias, const float* __restrict__ resid,
               float* __restrict__ C, int M, int Ncols, int K, int ldB, int ldC,
               int relu, int roundC) {
    extern __shared__ float smem[];

    const int tid  = threadIdx.x;
    const int lane = tid & 31;
    const int wid  = tid >> 5;
    const int warpM = (wid >> 1) * 64;
    const int warpN = (wid & 1) * 32;
    const int gm = blockIdx.x * 128;
    const int gn = blockIdx.y * 64;
    const int lt = lane & 3;
    const int lg = lane >> 2;

    float acc[4][4][4];
    #pragma unroll
    for (int mi = 0; mi < 4; mi++)
        #pragma unroll
        for (int nj = 0; nj < 4; nj++)
            #pragma unroll
            for (int r = 0; r < 4; r++) acc[mi][nj][r] = 0.f;

    const int nch = K >> 5;

    auto load_tiles = [&](int k0, int stage) {
        float* As = smem + stage * ASTG;
        float* Bs = smem + BOFF + stage * BSTG;
        #pragma unroll
        for (int i = 0; i < 8; i++) {
            int c  = tid + i * 128;        // 0..1023
            int m  = c >> 3;
            int k4 = (c & 7) << 2;
            cp16(As + m * AK + k4, A + (size_t)(gm + m) * K + k0 + k4);
        }
        #pragma unroll
        for (int i = 0; i < 4; i++) {
            int c  = tid + i * 128;        // 0..511
            int kr = c >> 4;
            int n4 = (c & 15) << 2;
            cp16(Bs + kr * BN2 + n4, Bm + (size_t)(k0 + kr) * ldB + gn + n4);
        }
    };

    load_tiles(0, 0);
    CP_COMMIT();

    unsigned a[2][4][4], b[2][4][2];

    for (int ch = 0; ch < nch; ch++) {
        int stage = ch & 1;
        if (ch + 1 < nch) load_tiles((ch + 1) << 5, stage ^ 1);
        CP_COMMIT();
        CP_WAIT1();
        __syncthreads();

        const float* Asb = smem + stage * ASTG;
        const float* Bsb = smem + BOFF + stage * BSTG;

        auto load_frag = [&](int kk, int buf) {
            #pragma unroll
            for (int mi = 0; mi < 4; mi++) {
                const float* p0 = Asb + (warpM + mi * 16 + lg) * AK + kk;
                const float* p1 = p0 + 8 * AK;
                a[buf][mi][0] = __float_as_uint(p0[lt]);
                a[buf][mi][1] = __float_as_uint(p1[lt]);
                a[buf][mi][2] = __float_as_uint(p0[lt + 4]);
                a[buf][mi][3] = __float_as_uint(p1[lt + 4]);
            }
            #pragma unroll
            for (int nj = 0; nj < 4; nj++) {
                int nc = warpN + nj * 8 + lg;
                b[buf][nj][0] = f2tf(Bsb[(kk + lt) * BN2 + nc]);
                b[buf][nj][1] = f2tf(Bsb[(kk + lt + 4) * BN2 + nc]);
            }
        };

        load_frag(0, 0);
        #pragma unroll
        for (int kks = 0; kks < 4; kks++) {
            int cur = kks & 1;
            if (kks < 3) load_frag((kks + 1) << 3, cur ^ 1);
            #pragma unroll
            for (int mi = 0; mi < 4; mi++)
                #pragma unroll
                for (int nj = 0; nj < 4; nj++)
                    mma_tf32(acc[mi][nj], a[cur][mi], b[cur][nj]);
        }
        __syncthreads();
    }

    // ---- epilogue ----
    #pragma unroll
    for (int mi = 0; mi < 4; mi++) {
        int r0 = gm + warpM + mi * 16 + lg;
        #pragma unroll
        for (int nj = 0; nj < 4; nj++) {
            int c0 = gn + warpN + nj * 8 + (lt << 1);
            #pragma unroll
            for (int r = 0; r < 4; r++) {
                int rowg = r0 + ((r >> 1) << 3);
                int colg = c0 + (r & 1);
                if (colg < Ncols) {
                    float v = acc[mi][nj][r];
                    if (bias)   v += bias[colg];
                    if (resid)  v += resid[(size_t)rowg * ldC + colg];
                    if (relu)   v = fmaxf(v, 0.f);
                    if (roundC) v = tf32f(v);
                    C[(size_t)rowg * ldC + colg] = v;
                }
            }
        }
    }
}

// ---------------- attention scores via tf32 mma: scale * Q K^T + causal ----------------
#define QP 68
#define KP 65
__global__ __launch_bounds__(128)
void attn_scores(const float* __restrict__ q, const float* __restrict__ k,
                 float* __restrict__ att) {
    int tb = blockIdx.x, sb = blockIdx.y, bh = blockIdx.z;
    if (sb > tb) return;
    int b = bh / NH, h = bh % NH;

    __shared__ float Qs[64 * QP];   // [m][d]
    __shared__ float Ks[64 * KP];   // [d][s]
    const int tid  = threadIdx.x;
    const int lane = tid & 31;
    const int wid  = tid >> 5;
    const int warpM = (wid >> 1) * 32;
    const int warpN = (wid & 1) * 32;
    const int lt = lane & 3;
    const int lg = lane >> 2;

    const float* qb = q + (size_t)b * TT * D + (size_t)h * HD;
    const float* kb = k + (size_t)b * TT * D + (size_t)h * HD;

    #pragma unroll
    for (int i = 0; i < 8; i++) {
        int c  = tid + i * 128;
        int m  = c >> 4;
        int d4 = (c & 15) << 2;
        *(float4*)(Qs + m * QP + d4) =
            *(const float4*)(qb + (size_t)(tb * 64 + m) * D + d4);
    }
    #pragma unroll
    for (int i = 0; i < 32; i++) {
        int c = tid + i * 128;
        int s = c >> 6;
        int d = c & 63;
        Ks[d * KP + s] = kb[(size_t)(sb * 64 + s) * D + d];
    }
    __syncthreads();

    float acc[2][4][4];
    #pragma unroll
    for (int mi = 0; mi < 2; mi++)
        #pragma unroll
        for (int nj = 0; nj < 4; nj++)
            #pragma unroll
            for (int r = 0; r < 4; r++) acc[mi][nj][r] = 0.f;

    #pragma unroll
    for (int kk = 0; kk < 64; kk += 8) {
        unsigned a[2][4], bfr[4][2];
        #pragma unroll
        for (int mi = 0; mi < 2; mi++) {
            const float* p0 = Qs + (warpM + mi * 16 + lg) * QP + kk;
            const float* p1 = p0 + 8 * QP;
            a[mi][0] = f2tf(p0[lt]);
            a[mi][1] = f2tf(p1[lt]);
            a[mi][2] = f2tf(p0[lt + 4]);
            a[mi][3] = f2tf(p1[lt + 4]);
        }
        #pragma unroll
        for (int nj = 0; nj < 4; nj++) {
            int nc = warpN + nj * 8 + lg;
            bfr[nj][0] = f2tf(Ks[(kk + lt) * KP + nc]);
            bfr[nj][1] = f2tf(Ks[(kk + lt + 4) * KP + nc]);
        }
        #pragma unroll
        for (int mi = 0; mi < 2; mi++)
            #pragma unroll
            for (int nj = 0; nj < 4; nj++)
                mma_tf32(acc[mi][nj], a[mi], bfr[nj]);
    }

    float* out = att + ((size_t)bh * TT + (size_t)tb * 64) * TT + (size_t)sb * 64;
    #pragma unroll
    for (int mi = 0; mi < 2; mi++) {
        int tl0 = warpM + mi * 16 + lg;
        #pragma unroll
        for (int nj = 0; nj < 4; nj++) {
            int sl0 = warpN + nj * 8 + (lt << 1);
            #pragma unroll
            for (int r = 0; r < 4; r++) {
                int tl = tl0 + ((r >> 1) << 3);
                int sl = sl0 + (r & 1);
                int tg = tb * 64 + tl;
                int sg = sb * 64 + sl;
                out[(size_t)tl * TT + sl] =
                    (sg <= tg) ? acc[mi][nj][r] * SCALE : -3.402823466e38f;
            }
        }
    }
}

// ---------------- attention row softmax (fast exp) ----------------
__global__ void attn_softmax(float* __restrict__ att) {
    int row = blockIdx.x;
    int t = row & (TT - 1);
    float* p = att + (size_t)row * TT;
    int L = ((t >> 6) + 1) << 6;
    int tid = threadIdx.x;

    float m = -FLT_MAX;
    for (int i = tid; i < L; i += 256) m = fmaxf(m, p[i]);
    __shared__ float sm[256], ss[256];
    sm[tid] = m; __syncthreads();
    #pragma unroll
    for (int off = 128; off > 0; off >>= 1) {
        if (tid < off) sm[tid] = fmaxf(sm[tid], sm[tid + off]);
        __syncthreads();
    }
    float gm = sm[0];

    float s = 0.f;
    for (int i = tid; i < L; i += 256) s += __expf(p[i] - gm);
    ss[tid] = s; __syncthreads();
    #pragma unroll
    for (int off = 128; off > 0; off >>= 1) {
        if (tid < off) ss[tid] += ss[tid + off];
        __syncthreads();
    }
    float inv = 1.f / ss[0];
    for (int i = tid; i < L; i += 256)
        p[i] = __expf(p[i] - gm) * inv;
}

// ---------------- attention PV via tf32 mma: O = P @ V ----------------
#define PP 68
#define VP 68
__global__ __launch_bounds__(128)
void attn_pv(const float* __restrict__ att, const float* __restrict__ v,
             float* __restrict__ o) {
    int tb = blockIdx.x, bh = blockIdx.y;
    int b = bh / NH, h = bh % NH;

    __shared__ float Ps[64 * PP];   // [t][s]
    __shared__ float Vs[64 * VP];   // [s][d]
    const int tid  = threadIdx.x;
    const int lane = tid & 31;
    const int wid  = tid >> 5;
    const int warpM = (wid >> 1) * 32;
    const int warpN = (wid & 1) * 32;
    const int lt = lane & 3;
    const int lg = lane >> 2;

    const float* arow = att + ((size_t)bh * TT + (size_t)tb * 64) * TT;
    const float* vb = v + (size_t)b * TT * D + (size_t)h * HD;
    int Smax = (tb + 1) * 64;

    float acc[2][4][4];
    #pragma unroll
    for (int mi = 0; mi < 2; mi++)
        #pragma unroll
        for (int nj = 0; nj < 4; nj++)
            #pragma unroll
            for (int r = 0; r < 4; r++) acc[mi][nj][r] = 0.f;

    for (int s0 = 0; s0 < Smax; s0 += 64) {
        #pragma unroll
        for (int i = 0; i < 8; i++) {
            int c  = tid + i * 128;
            int m  = c >> 4;
            int s4 = (c & 15) << 2;
            *(float4*)(Ps + m * PP + s4) =
                *(const float4*)(arow + (size_t)m * TT + s0 + s4);
            *(float4*)(Vs + m * VP + s4) =
                *(const float4*)(vb + (size_t)(s0 + m) * D + s4);
        }
        __syncthreads();

        #pragma unroll
        for (int kk = 0; kk < 64; kk += 8) {
            unsigned a[2][4], bfr[4][2];
            #pragma unroll
            for (int mi = 0; mi < 2; mi++) {
                const float* p0 = Ps + (warpM + mi * 16 + lg) * PP + kk;
                const float* p1 = p0 + 8 * PP;
                a[mi][0] = f2tf(p0[lt]);
                a[mi][1] = f2tf(p1[lt]);
                a[mi][2] = f2tf(p0[lt + 4]);
                a[mi][3] = f2tf(p1[lt + 4]);
            }
            #pragma unroll
            for (int nj = 0; nj < 4; nj++) {
                int nc = warpN + nj * 8 + lg;
                bfr[nj][0] = f2tf(Vs[(kk + lt) * VP + nc]);
                bfr[nj][1] = f2tf(Vs[(kk + lt + 4) * VP + nc]);
            }
            #pragma unroll
            for (int mi = 0; mi < 2; mi++)
                #pragma unroll
                for (int nj = 0; nj < 4; nj++)
                    mma_tf32(acc[mi][nj], a[mi], bfr[nj]);
        }
        __syncthreads();
    }

    float* ob = o + (size_t)(b * TT + tb * 64) * D + (size_t)h * HD;
    #pragma unroll
    for (int mi = 0; mi < 2; mi++) {
        int tl0 = warpM + mi * 16 + lg;
        #pragma unroll
        for (int nj = 0; nj < 4; nj++) {
            int dl0 = warpN + nj * 8 + (lt << 1);
            #pragma unroll
            for (int r = 0; r < 4; r++) {
                int tl = tl0 + ((r >> 1) << 3);
                int dl = dl0 + (r & 1);
                ob[(size_t)tl * D + dl] = tf32f(acc[mi][nj][r]);
            }
        }
    }
}

// ---------------- per-row NLL over vocab ----------------
__global__ void nll_kernel(const float* __restrict__ logits,
                           const int* __restrict__ targets,
                           float* __restrict__ nll) {
    int row = blockIdx.x;
    const float* lr = logits + (size_t)row * VV;
    int tid = threadIdx.x;
    __shared__ float red[256];

    float m = -FLT_MAX;
    for (int i = tid; i < VV; i += 256) m = fmaxf(m, lr[i]);
    red[tid] = m; __syncthreads();
    #pragma unroll
    for (int off = 128; off > 0; off >>= 1) {
        if (tid < off) red[tid] = fmaxf(red[tid], red[tid + off]);
        __syncthreads();
    }
    float gm = red[0];
    __syncthreads();

    float s0 = 0.f, s1 = 0.f, s2 = 0.f, s3 = 0.f;
    int i = tid;
    for (; i + 768 < VV; i += 1024) {
        s0 += __expf(lr[i]       - gm);
        s1 += __expf(lr[i + 256] - gm);
        s2 += __expf(lr[i + 512] - gm);
        s3 += __expf(lr[i + 768] - gm);
    }
    for (; i < VV; i += 256) s0 += __expf(lr[i] - gm);
    red[tid] = (s0 + s1) + (s2 + s3); __syncthreads();
    #pragma unroll
    for (int off = 128; off > 0; off >>= 1) {
        if (tid < off) red[tid] += red[tid + off];
        __syncthreads();
    }
    if (tid == 0)
        nll[row] = gm + logf(red[0]) - lr[targets[row]];
}

__global__ void loss_kernel(const float* __restrict__ nll, float* __restrict__ dst,
                            int nextra) {
    __shared__ float red[256];
    int tid = threadIdx.x;
    float s = 0.f;
    for (int i = tid; i < BT; i += 256) s += nll[i];
    red[tid] = s; __syncthreads();
    #pragma unroll
    for (int off = 128; off > 0; off >>= 1) {
        if (tid < off) red[tid] += red[tid + off];
        __syncthreads();
    }
    if (tid == 0) {
        float loss = red[0] * (1.f / BT);
        for (int i = 0; i < nextra; i++) dst[i] = loss;
    }
}

// ---------------- launch ----------------
extern "C" void kernel_launch(void* const* d_in, const int* in_sizes, int n_in,
                              void* d_out, int out_size) {
    const int*   idx     = (const int*)  d_in[0];
    const int*   targets = (const int*)  d_in[1];
    const float* tok_emb = (const float*)d_in[2];
    const float* pos_emb = (const float*)d_in[3];
    const float* Wq      = (const float*)d_in[4];
    const float* Wk      = (const float*)d_in[5];
    const float* Wv      = (const float*)d_in[6];
    const float* Wo      = (const float*)d_in[7];
    const float* bo      = (const float*)d_in[8];
    const float* ln1_g   = (const float*)d_in[9];
    const float* ln1_b   = (const float*)d_in[10];
    const float* ln2_g   = (const float*)d_in[11];
    const float* ln2_b   = (const float*)d_in[12];
    const float* W1      = (const float*)d_in[13];
    const float* b1      = (const float*)d_in[14];
    const float* W2      = (const float*)d_in[15];
    const float* b2      = (const float*)d_in[16];
    const float* Wlm     = (const float*)d_in[17];
    const float* blm     = (const float*)d_in[18];

    float *x, *h, *q, *k, *v, *o, *ff, *att, *nll, *wlm;
    cudaGetSymbolAddress((void**)&x,   g_x);
    cudaGetSymbolAddress((void**)&h,   g_h);
    cudaGetSymbolAddress((void**)&q,   g_q);
    cudaGetSymbolAddress((void**)&k,   g_k);
    cudaGetSymbolAddress((void**)&v,   g_v);
    cudaGetSymbolAddress((void**)&o,   g_o);
    cudaGetSymbolAddress((void**)&ff,  g_ff);
    cudaGetSymbolAddress((void**)&att, g_att);
    cudaGetSymbolAddress((void**)&nll, g_nll);
    cudaGetSymbolAddress((void**)&wlm, g_wlm);

    cudaFuncSetAttribute(gemm_tf32, cudaFuncAttributeMaxDynamicSharedMemorySize, GSMEM);

    // pad LM-head weight to VPAD columns (zero-filled, vectorizable)
    pad_wlm_kernel<<<dim3((VPAD + 255) / 256, D), 256>>>(Wlm, wlm);

    embed_kernel<<<(BT * D + 255) / 256, 256>>>(idx, tok_emb, pos_emb, x);

    dim3 gD(BT / 128, D / 64);               // 32 x 12
    dim3 gF(BT / 128, FF / 64);              // 32 x 48
    dim3 gV(BT / 128, VPAD / 64);            // 32 x 786

    for (int l = 0; l < NL; l++) {
        const float* wq = Wq + (size_t)l * D * D;
        const float* wk = Wk + (size_t)l * D * D;
        const float* wv = Wv + (size_t)l * D * D;
        const float* wo = Wo + (size_t)l * D * D;
        const float* w1 = W1 + (size_t)l * D * FF;
        const float* w2 = W2 + (size_t)l * FF * D;

        ln_kernel<<<BT, 256>>>(x, ln1_g + (size_t)l * D, ln1_b + (size_t)l * D, h);
        gemm_tf32<<<gD, 128, GSMEM>>>(h, wq, nullptr, nullptr, q, BT, D, D, D, D, 0, 0);
        gemm_tf32<<<gD, 128, GSMEM>>>(h, wk, nullptr, nullptr, k, BT, D, D, D, D, 0, 0);
        gemm_tf32<<<gD, 128, GSMEM>>>(h, wv, nullptr, nullptr, v, BT, D, D, D, D, 0, 0);

        attn_scores<<<dim3(TT / 64, TT / 64, BH), 128>>>(q, k, att);
        attn_softmax<<<BH * TT, 256>>>(att);
        attn_pv<<<dim3(TT / 64, BH), 128>>>(att, v, o);

        gemm_tf32<<<gD, 128, GSMEM>>>(o, wo, bo + (size_t)l * D, x, x, BT, D, D, D, D, 0, 0);

        ln_kernel<<<BT, 256>>>(x, ln2_g + (size_t)l * D, ln2_b + (size_t)l * D, h);
        gemm_tf32<<<gF, 128, GSMEM>>>(h, w1, b1 + (size_t)l * FF, nullptr, ff, BT, FF, D, FF, FF, 1, 1);
        gemm_tf32<<<gD, 128, GSMEM>>>(ff, w2, b2 + (size_t)l * D, x, x, BT, D, FF, D, D, 0, 0);
    }

    // rounded copy of x for the LM head A operand
    round_kernel<<<1024, 256>>>(x, h, (long long)BT * D);

    float* logits = (float*)d_out;
    gemm_tf32<<<gV, 128, GSMEM>>>(h, wlm, blm, nullptr, logits, BT, VV, D, VPAD, VV, 0, 0);

    long long btv = (long long)BT * VV;
    if ((long long)out_size > btv) {
        nll_kernel<<<BT, 256>>>(logits, targets, nll);
        loss_kernel<<<1, 256>>>(nll, logits + btv, (int)((long long)out_size - btv));
    }
}